// round 3
// baseline (speedup 1.0000x reference)
#include <cuda_runtime.h>
#include <math.h>

#define NBLK 128
#define NTHR 256
#define HID  128
#define BINS 513
#define WIN  1024
#define ENCN 256

// ---------------- device scratch ----------------
__device__ float g_h1[HID], g_h2[HID], g_h1b[HID], g_h2b[HID];
__device__ float g_specr[BINS], g_speci[BINS];
__device__ float g_y1[WIN];
__device__ float g_enc[ENCN];
__device__ float g_est[ENCN];
__device__ unsigned g_cnt[8];        // per-stage arrival counters (reset each launch)
__device__ unsigned g_done[NBLK];    // end-of-kernel flags

__device__ __forceinline__ float wsum(float v){
#pragma unroll
    for (int o = 16; o > 0; o >>= 1) v += __shfl_xor_sync(0xffffffffu, v, o);
    return v;
}
__device__ __forceinline__ float sigm(float x){ return 1.0f/(1.0f+__expf(-x)); }

// Producer-side: CTA-level arrival on stage counter s.
__device__ __forceinline__ void signal(int s){
    __threadfence();
    __syncthreads();
    if (threadIdx.x == 0) atomicAdd(&g_cnt[s], 1u);
}
// Consumer-side: per-warp spin until counter s reaches tgt.
__device__ __forceinline__ void waitcnt(int s, unsigned tgt){
    if ((threadIdx.x & 31) == 0){
        volatile unsigned* c = &g_cnt[s];
        while (*c < tgt) {}
    }
    __syncwarp();
    __threadfence();
}

// Preload LSTM unit j's weights/biases/prev-state into registers.
template<int NX, int NXR>
__device__ __forceinline__ void lstm_preload(
    int j, int lane,
    const float* __restrict__ wih, const float* __restrict__ whh,
    const float* __restrict__ bih, const float* __restrict__ bhh,
    const float* __restrict__ hvec,
    float wi[4][17], float wh[4][4], float hr[4], float bsum[4])
{
#pragma unroll
    for (int g = 0; g < 4; g++){
        const float* w = wih + (size_t)(g*HID + j)*NX;
#pragma unroll
        for (int i = 0; i < NXR; i++){
            int k = lane + 32*i;
            wi[g][i] = ((NX & 31) == 0 || k < NX) ? w[k] : 0.f;
        }
        const float* whp = whh + (size_t)(g*HID + j)*HID;
#pragma unroll
        for (int i = 0; i < 4; i++) wh[g][i] = whp[lane + 32*i];
        bsum[g] = bih[g*HID + j] + bhh[g*HID + j];
    }
#pragma unroll
    for (int i = 0; i < 4; i++) hr[i] = hvec[lane + 32*i];
}

template<int NXR>
__device__ __forceinline__ void lstm_fire(
    int lane, const float wi[4][17], const float wh[4][4],
    const float* xr, const float hr[4], const float bsum[4],
    float cprev, float* hdst, float* hout, float* cout)
{
    float a[4];
#pragma unroll
    for (int g = 0; g < 4; g++){
        float acc = 0.f;
#pragma unroll
        for (int i = 0; i < NXR; i++) acc = fmaf(wi[g][i], xr[i], acc);
#pragma unroll
        for (int i = 0; i < 4; i++)   acc = fmaf(wh[g][i], hr[i], acc);
        a[g] = wsum(acc) + bsum[g];
    }
    if (lane == 0){
        float c2 = sigm(a[1])*cprev + sigm(a[0])*tanhf(a[2]);
        float h2 = sigm(a[3])*tanhf(c2);
        *hdst = h2; *hout = h2; *cout = c2;
    }
}

__device__ __forceinline__ int skew(int i){ return i + (i >> 5); }

__global__ void __launch_bounds__(NTHR) dtln_kernel(
    const float* __restrict__ mag,   const float* __restrict__ phase,
    const float* __restrict__ st1,   const float* __restrict__ st2,
    const float* __restrict__ wih10, const float* __restrict__ whh10,
    const float* __restrict__ bih10, const float* __restrict__ bhh10,
    const float* __restrict__ wih11, const float* __restrict__ whh11,
    const float* __restrict__ bih11, const float* __restrict__ bhh11,
    const float* __restrict__ d1w,   const float* __restrict__ d1b,
    const float* __restrict__ encw,  const float* __restrict__ gamma_,
    const float* __restrict__ beta_,
    const float* __restrict__ wih20, const float* __restrict__ whh20,
    const float* __restrict__ bih20, const float* __restrict__ bhh20,
    const float* __restrict__ wih21, const float* __restrict__ whh21,
    const float* __restrict__ bih21, const float* __restrict__ bhh21,
    const float* __restrict__ d2w,   const float* __restrict__ d2b,
    const float* __restrict__ decw,
    float* __restrict__ out)
{
    const int tid  = threadIdx.x;
    const int lane = tid & 31;
    const int wid  = tid >> 5;
    const int cta  = blockIdx.x;
    const int gw   = cta * 8 + wid;      // 0..1023

    __shared__ float2 s_tw[WIN + 32];    // skewed twiddle table (G4 only)
    __shared__ float  s_encn[ENCN];
    __shared__ float  s_red[8];

    // Decoder row preload (every warp owns one output row).
    float decr[8];
    {
        const float* wr = decw + (size_t)gw*ENCN;
#pragma unroll
        for (int i = 0; i < 8; i++) decr[i] = wr[lane + 32*i];
    }

    // Stage counters legend:
    // 0: LSTM1a done (16 CTAs)   1: LSTM1b done (16)
    // 2: dense1/spec done (32)   3: iDFT done (32)
    // 4: encoder done (32)       5: LSTM2a done (16)
    // 6: LSTM2b done (16)        7: dense2 done (32)

    if (cta < 16){
        // ===================== G1: LSTM1 layer0 =====================
        float wi[4][17], wh4[4][4], hr[4], bsum[4];
        int j = gw;
        lstm_preload<BINS,17>(j, lane, wih10, whh10, bih10, bhh10, st1, wi, wh4, hr, bsum);
        float cprev = st1[2*HID + j];
        float xr[17];
#pragma unroll
        for (int i = 0; i < 17; i++){ int k = lane + 32*i; xr[i] = (k < BINS) ? mag[k] : 0.f; }
        lstm_fire<17>(lane, wi, wh4, xr, hr, bsum, cprev,
                      &g_h1[j], &out[WIN + j], &out[WIN + 2*HID + j]);
        signal(0);
    }
    else if (cta < 32){
        // ===================== G2: LSTM1 layer1 =====================
        float wi[4][17], wh4[4][4], hr[4], bsum[4];
        int j = gw - 128;
        lstm_preload<HID,4>(j, lane, wih11, whh11, bih11, bhh11, st1 + HID, wi, wh4, hr, bsum);
        float cprev = st1[3*HID + j];
        waitcnt(0, 16);
        float xr[4];
#pragma unroll
        for (int i = 0; i < 4; i++) xr[i] = g_h1[lane + 32*i];
        lstm_fire<4>(lane, wi, wh4, xr, hr, bsum, cprev,
                     &g_h2[j], &out[WIN + HID + j], &out[WIN + 3*HID + j]);
        signal(1);
    }
    else if (cta < 64){
        // ============ G3: dense1/spectrum, then LSTM2a or LSTM2b ============
        int dw = gw - 256;                 // 0..255
        int r0 = dw, r1 = dw + 256;
        float w0[4], w1[4], w2[4];
        float b0, b1, b2 = 0.f, m0, m1, m2 = 0.f;
        float c0, s0, c1, s1, c2v = 1.f, s2v = 0.f;
        {
            const float* wr0 = d1w + (size_t)r0*HID;
            const float* wr1 = d1w + (size_t)r1*HID;
#pragma unroll
            for (int i = 0; i < 4; i++){ w0[i] = wr0[lane+32*i]; w1[i] = wr1[lane+32*i]; }
            b0 = d1b[r0]; b1 = d1b[r1];
            m0 = mag[r0]; m1 = mag[r1];
            sincosf(phase[r0], &s0, &c0);
            sincosf(phase[r1], &s1, &c1);
            if (dw == 0){
                const float* wr2 = d1w + (size_t)512*HID;
#pragma unroll
                for (int i = 0; i < 4; i++) w2[i] = wr2[lane+32*i];
                b2 = d1b[512]; m2 = mag[512];
                sincosf(phase[512], &s2v, &c2v);
            }
        }
        // second role preload
        float wi[4][17], wh4[4][4], hr[4], bsum[4], cprev;
        float gam = 0.f, bet = 0.f;
        if (cta < 48){
            int j = gw - 256;
            lstm_preload<ENCN,8>(j, lane, wih20, whh20, bih20, bhh20, st2, wi, wh4, hr, bsum);
            cprev = st2[2*HID + j];
            gam = gamma_[tid]; bet = beta_[tid];
        } else {
            int j = gw - 384;
            lstm_preload<HID,4>(j, lane, wih21, whh21, bih21, bhh21, st2 + HID, wi, wh4, hr, bsum);
            cprev = st2[3*HID + j];
        }

        waitcnt(1, 16);
        {
            float xr[4];
#pragma unroll
            for (int i = 0; i < 4; i++) xr[i] = g_h2[lane + 32*i];
            float a0 = 0.f, a1 = 0.f, a2 = 0.f;
#pragma unroll
            for (int i = 0; i < 4; i++){
                a0 = fmaf(w0[i], xr[i], a0);
                a1 = fmaf(w1[i], xr[i], a1);
                a2 = fmaf((dw==0)?w2[i]:0.f, xr[i], a2);
            }
            a0 = wsum(a0); a1 = wsum(a1); a2 = wsum(a2);
            if (lane == 0){
                float e0 = sigm(a0 + b0) * m0;
                float e1 = sigm(a1 + b1) * m1;
                g_specr[r0] = e0 * c0;  g_speci[r0] = e0 * s0;
                g_specr[r1] = e1 * c1;  g_speci[r1] = e1 * s1;
                if (dw == 0){
                    float e2 = sigm(a2 + b2) * m2;
                    g_specr[512] = e2 * c2v;  g_speci[512] = e2 * s2v;
                }
            }
        }
        signal(2);

        if (cta < 48){
            // ---- instance norm + LSTM2 layer0 ----
            waitcnt(4, 32);
            float v  = g_enc[tid];
            float t1 = wsum(v);
            if (lane == 0) s_red[wid] = t1;
            __syncthreads();
            float tot = 0.f;
#pragma unroll
            for (int i = 0; i < 8; i++) tot += s_red[i];
            float mean = tot * (1.0f/ENCN);
            float d = v - mean;
            float t2 = wsum(d*d);
            __syncthreads();
            if (lane == 0) s_red[wid] = t2;
            __syncthreads();
            float tot2 = 0.f;
#pragma unroll
            for (int i = 0; i < 8; i++) tot2 += s_red[i];
            float rstd = rsqrtf(tot2 * (1.0f/ENCN) + 1e-7f);
            s_encn[tid] = d * rstd * gam + bet;
            __syncthreads();

            int j = gw - 256;
            float xr[8];
#pragma unroll
            for (int i = 0; i < 8; i++) xr[i] = s_encn[lane + 32*i];
            lstm_fire<8>(lane, wi, wh4, xr, hr, bsum, cprev,
                         &g_h1b[j], &out[WIN + 4*HID + j], &out[WIN + 6*HID + j]);
            signal(5);
        } else {
            // ---- LSTM2 layer1 ----
            waitcnt(5, 16);
            int j = gw - 384;
            float xr[4];
#pragma unroll
            for (int i = 0; i < 4; i++) xr[i] = g_h1b[lane + 32*i];
            lstm_fire<4>(lane, wi, wh4, xr, hr, bsum, cprev,
                         &g_h2b[j], &out[WIN + 5*HID + j], &out[WIN + 7*HID + j]);
            signal(6);
        }
    }
    else if (cta < 96){
        // ===================== G4: iDFT then encoder =====================
        int w = gw - 512;                 // 0..255
        float wrow[32];
        {
            const float* wr = encw + (size_t)w*WIN;
#pragma unroll
            for (int i = 0; i < 32; i++) wrow[i] = wr[lane + 32*i];
        }
        // build skewed twiddle table: tw[i] = (cos, sin)(2*pi*i/1024)
        for (int i = tid; i < WIN; i += NTHR){
            float s, c; sincospif((float)i * (1.0f/512.0f), &s, &c);
            s_tw[skew(i)] = make_float2(c, s);
        }
        __syncthreads();

        waitcnt(2, 32);
        {
            int n0 = w * 4;
            float sr0 = g_specr[0];
            float nyq = g_specr[512];
            float acc[4] = {0.f, 0.f, 0.f, 0.f};
#pragma unroll
            for (int t = 0; t < 16; t++){
                int k = 1 + lane + 32*t;
                if (k < 512){
                    float sr = g_specr[k], si = g_speci[k];
                    int base = (k * n0) & (WIN-1);
#pragma unroll
                    for (int q = 0; q < 4; q++){
                        int idx = (base + q*k) & (WIN-1);
                        float2 cs = s_tw[skew(idx)];
                        acc[q] += sr*cs.x - si*cs.y;
                    }
                }
            }
#pragma unroll
            for (int q = 0; q < 4; q++){
                float a = wsum(acc[q]);
                if (lane == 0){
                    int n = n0 + q;
                    float ny = (n & 1) ? -nyq : nyq;
                    g_y1[n] = (sr0 + 2.0f*a + ny) * (1.0f/1024.0f);
                }
            }
        }
        signal(3);

        waitcnt(3, 32);
        {
            float acc = 0.f;
#pragma unroll
            for (int i = 0; i < 32; i++) acc = fmaf(wrow[i], g_y1[lane + 32*i], acc);
            acc = wsum(acc);
            if (lane == 0) g_enc[w] = acc;
        }
        signal(4);
    }
    else {
        // ===================== G6: dense2 mask * enc =====================
        int r = gw - 768;                 // 0..255
        float d2r[4];
        {
            const float* wr = d2w + (size_t)r*HID;
#pragma unroll
            for (int i = 0; i < 4; i++) d2r[i] = wr[lane + 32*i];
        }
        float d2bias = d2b[r];
        waitcnt(6, 16);
        waitcnt(4, 32);
        {
            float xr[4];
#pragma unroll
            for (int i = 0; i < 4; i++) xr[i] = g_h2b[lane + 32*i];
            float acc = 0.f;
#pragma unroll
            for (int i = 0; i < 4; i++) acc = fmaf(d2r[i], xr[i], acc);
            acc = wsum(acc);
            if (lane == 0) g_est[r] = sigm(acc + d2bias) * g_enc[r];
        }
        signal(7);
    }

    // ===================== S9: decoder (all warps) =====================
    waitcnt(7, 32);
    {
        float xr[8];
#pragma unroll
        for (int i = 0; i < 8; i++) xr[i] = g_est[lane + 32*i];
        float acc = 0.f;
#pragma unroll
        for (int i = 0; i < 8; i++) acc = fmaf(decr[i], xr[i], acc);
        acc = wsum(acc);
        if (lane == 0) out[gw] = acc;
    }

    // ===================== cleanup: counter reset =====================
    __threadfence();
    __syncthreads();
    if (tid == 0) *((volatile unsigned*)&g_done[cta]) = 1u;
    if (cta == 0){
        if (tid < NBLK){
            volatile unsigned* f = &g_done[tid];
            while (*f == 0u) {}
        }
        __syncthreads();
        if (tid < 8)    g_cnt[tid] = 0u;
        if (tid < NBLK) g_done[tid] = 0u;
    }
}

extern "C" void kernel_launch(void* const* d_in, const int* in_sizes, int n_in,
                              void* d_out, int out_size)
{
    (void)in_sizes; (void)n_in; (void)out_size;
    dtln_kernel<<<NBLK, NTHR>>>(
        (const float*)d_in[0],  (const float*)d_in[1],
        (const float*)d_in[2],  (const float*)d_in[3],
        (const float*)d_in[4],  (const float*)d_in[5],
        (const float*)d_in[6],  (const float*)d_in[7],
        (const float*)d_in[8],  (const float*)d_in[9],
        (const float*)d_in[10], (const float*)d_in[11],
        (const float*)d_in[12], (const float*)d_in[13],
        (const float*)d_in[14], (const float*)d_in[15],
        (const float*)d_in[16],
        (const float*)d_in[17], (const float*)d_in[18],
        (const float*)d_in[19], (const float*)d_in[20],
        (const float*)d_in[21], (const float*)d_in[22],
        (const float*)d_in[23], (const float*)d_in[24],
        (const float*)d_in[25], (const float*)d_in[26],
        (const float*)d_in[27],
        (float*)d_out);
}